// round 7
// baseline (speedup 1.0000x reference)
#include <cuda_runtime.h>
#include <math.h>

#define Bsz 4
#define Lsz 1024
#define Dsz 512
#define Hsz 8
#define DKsz 64

// ---------------- scratch (static device globals; no allocation) ----------------
__device__ float g_Q[Bsz*Lsz*Dsz];
__device__ float g_K[Bsz*Lsz*Dsz];
__device__ float g_V[Bsz*Lsz*Dsz];
__device__ float g_QP[Bsz*Lsz*Dsz];
__device__ float g_KP[Bsz*Lsz*Dsz];
__device__ float g_EM[Bsz*Lsz*Lsz];              // exp(1 - m)
__device__ float g_G[Bsz*Lsz];
__device__ float g_S[(size_t)Bsz*Hsz*Lsz*Lsz];   // exp(scores)
__device__ float g_Z[Bsz*Hsz*Lsz];               // softmax-1 row sums (atomic)
__device__ float g_CTX[Bsz*Lsz*Dsz];

// ---------------- helpers ----------------
__device__ __forceinline__ unsigned f2tf(float f) {
    unsigned u;
    asm("cvt.rna.tf32.f32 %0, %1;" : "=r"(u) : "f"(f));
    return u;
}

__device__ __forceinline__ void mma_tf32(float c[4], const unsigned a[4], const unsigned b[2]) {
    asm volatile(
        "mma.sync.aligned.m16n8k8.row.col.f32.tf32.tf32.f32 "
        "{%0,%1,%2,%3}, {%4,%5,%6,%7}, {%8,%9}, {%0,%1,%2,%3};"
        : "+f"(c[0]), "+f"(c[1]), "+f"(c[2]), "+f"(c[3])
        : "r"(a[0]), "r"(a[1]), "r"(a[2]), "r"(a[3]), "r"(b[0]), "r"(b[1]));
}

__device__ __forceinline__ void cp_async16(void* smem, const void* gmem) {
    unsigned saddr = (unsigned)__cvta_generic_to_shared(smem);
    asm volatile("cp.async.cg.shared.global [%0], [%1], 16;" :: "r"(saddr), "l"(gmem));
}
__device__ __forceinline__ void cp_commit() { asm volatile("cp.async.commit_group;"); }
template<int N>
__device__ __forceinline__ void cp_wait() { asm volatile("cp.async.wait_group %0;" :: "n"(N)); }

// ---------------- tf32 GEMM core, 3-stage pipeline, ONE sync per iter ----------------
// Per iter: cp_wait (stage cur landed) -> __syncthreads (visibility + all warps
// finished iter-1) -> prefetch(it+2) into stage (it-1)%3 (safe post-sync) -> compute.
template<int BM, int BN, bool BT, int MT, int NT>
__device__ __forceinline__ void gemm_core(
    const float* __restrict__ A, int lda,
    const float* __restrict__ B, int ldb,
    int K, float (&acc)[MT][NT][4])
{
    constexpr int BK = 16;
    constexpr int APITCH = BK + 4;
    constexpr int BPITCH = BT ? (BK + 4) : (BN + 8);
    constexpr int BROWS  = BT ? BN : BK;

    extern __shared__ float dynsm[];
    float* As = dynsm;
    float* Bs = dynsm + 3 * BM * APITCH;

    const int tid = threadIdx.x;
    const int lane = tid & 31;
    const int wid = tid >> 5;
    const int wm0 = (wid & 3) * (BM / 4);
    const int wn0 = (wid >> 2) * (BN / 2);

    constexpr int ALD = (BM * BK / 4) / 256;
    constexpr int BLD = (BT ? (BN * BK / 4) : (BK * BN / 4)) / 256;

    auto prefetch = [&](int k0, int s) {
        float* Asl = As + s * BM * APITCH;
        float* Bsl = Bs + s * BROWS * BPITCH;
        #pragma unroll
        for (int i = 0; i < ALD; i++) {
            int idx = tid + i * 256;
            int row = idx >> 2, kq = idx & 3;
            cp_async16(&Asl[row * APITCH + kq * 4], A + (size_t)row * lda + k0 + kq * 4);
        }
        #pragma unroll
        for (int i = 0; i < BLD; i++) {
            int idx = tid + i * 256;
            if constexpr (BT) {
                int row = idx >> 2, kq = idx & 3;
                cp_async16(&Bsl[row * BPITCH + kq * 4], B + (size_t)row * ldb + k0 + kq * 4);
            } else {
                int k = idx / (BN / 4), nq = idx % (BN / 4);
                cp_async16(&Bsl[k * BPITCH + nq * 4], B + (size_t)(k0 + k) * ldb + nq * 4);
            }
        }
        cp_commit();
    };

    const int nIter = K / BK;
    prefetch(0, 0);
    if (nIter > 1) prefetch(BK, 1);

    for (int it = 0; it < nIter; it++) {
        if (it + 1 < nIter) cp_wait<1>(); else cp_wait<0>();
        __syncthreads();
        if (it + 2 < nIter) prefetch((it + 2) * BK, (it + 2) % 3);

        const int cur = it % 3;
        const float* Asl = As + cur * BM * APITCH;
        const float* Bsl = Bs + cur * BROWS * BPITCH;

        #pragma unroll
        for (int ks = 0; ks < 2; ks++) {
            unsigned af[MT][4];
            unsigned bf[NT][2];
            const int kk = ks * 8 + (lane & 3);
            #pragma unroll
            for (int mt = 0; mt < MT; mt++) {
                int row = wm0 + mt * 16 + (lane >> 2);
                af[mt][0] = f2tf(Asl[row * APITCH + kk]);
                af[mt][1] = f2tf(Asl[(row + 8) * APITCH + kk]);
                af[mt][2] = f2tf(Asl[row * APITCH + kk + 4]);
                af[mt][3] = f2tf(Asl[(row + 8) * APITCH + kk + 4]);
            }
            #pragma unroll
            for (int nt = 0; nt < NT; nt++) {
                int n = wn0 + nt * 8 + (lane >> 2);
                if constexpr (BT) {
                    bf[nt][0] = f2tf(Bsl[n * BPITCH + kk]);
                    bf[nt][1] = f2tf(Bsl[n * BPITCH + kk + 4]);
                } else {
                    bf[nt][0] = f2tf(Bsl[kk * BPITCH + n]);
                    bf[nt][1] = f2tf(Bsl[(kk + 4) * BPITCH + n]);
                }
            }
            #pragma unroll
            for (int mt = 0; mt < MT; mt++)
                #pragma unroll
                for (int nt = 0; nt < NT; nt++)
                    mma_tf32(acc[mt][nt], af[mt], bf[nt]);
        }
    }
}

// smem byte sizes
#define PROJ_SMEM  ((3*128*20 + 3*16*136) * 4)   // 56832
#define NTG_SMEM   ((3*128*20 + 3*128*20) * 4)   // 61440
#define CTXF_SMEM  ((3*128*20*2 + 3*16*72 + 128) * 4)  // 75776

// ---------------- batched projections / dense ----------------
struct ProjArgs {
    const float* A[5];
    const float* W[5];
    const float* bias[5];
    float* C[5];
};

__global__ void __launch_bounds__(256, 2) proj_gemm_kernel(ProjArgs args, int N, int K)
{
    const int z = blockIdx.z;
    float acc[2][8][4] = {};
    const float* Ab = args.A[z] + (size_t)blockIdx.y * 128 * K;
    const float* Bb = args.W[z] + blockIdx.x * 128;
    gemm_core<128, 128, false, 2, 8>(Ab, K, Bb, N, K, acc);

    const float* bias = args.bias[z];
    float* C = args.C[z];
    int lane = threadIdx.x & 31, wid = threadIdx.x >> 5;
    int rowBase = blockIdx.y * 128 + (wid & 3) * 32 + (lane >> 2);
    int colBase = blockIdx.x * 128 + (wid >> 2) * 64 + 2 * (lane & 3);
    #pragma unroll
    for (int mt = 0; mt < 2; mt++)
        #pragma unroll
        for (int nt = 0; nt < 8; nt++) {
            int row = rowBase + mt * 16;
            int col = colBase + nt * 8;
            float b0 = bias[col], b1 = bias[col + 1];
            *(float2*)&C[(size_t)row * N + col] =
                make_float2(acc[mt][nt][0] + b0, acc[mt][nt][1] + b1);
            *(float2*)&C[(size_t)(row + 8) * N + col] =
                make_float2(acc[mt][nt][2] + b0, acc[mt][nt][3] + b1);
        }
}

// ---------------- merged m + score GEMM launch ----------------
__global__ void __launch_bounds__(256, 2) ms_gemm_kernel(float* __restrict__ m_out)
{
    const int zz = blockIdx.z;
    int lane = threadIdx.x & 31, wid = threadIdx.x >> 5;
    int fcol = lane & 3;

    if (zz < Bsz) {
        const float SCALE = 0.04419417382415922f; // 1/sqrt(512)
        const int zb = zz;
        float acc[2][8][4] = {};
        const float* Ab = g_QP + (size_t)zb * Lsz * Dsz + (size_t)blockIdx.y * 128 * Dsz;
        const float* Bb = g_KP + (size_t)zb * Lsz * Dsz + (size_t)blockIdx.x * 128 * Dsz;
        gemm_core<128, 128, true, 2, 8>(Ab, Dsz, Bb, Dsz, Dsz, acc);

        float* Mo = m_out + (size_t)zb * Lsz * Lsz;
        float* Eo = g_EM + (size_t)zb * Lsz * Lsz;
        int rowBase = blockIdx.y * 128 + (wid & 3) * 32 + (lane >> 2);
        int colBase = blockIdx.x * 128 + (wid >> 2) * 64 + 2 * fcol;
        #pragma unroll
        for (int mt = 0; mt < 2; mt++)
            #pragma unroll
            for (int nt = 0; nt < 8; nt++) {
                int row = rowBase + mt * 16;
                int col = colBase + nt * 8;
                #pragma unroll
                for (int h = 0; h < 2; h++) {
                    int r = row + h * 8;
                    float s0 = 1.0f / (1.0f + __expf(-acc[mt][nt][2*h] * SCALE));
                    float s1 = 1.0f / (1.0f + __expf(-acc[mt][nt][2*h+1] * SCALE));
                    *(float2*)&Mo[(size_t)r * Lsz + col] = make_float2(s0, s1);
                    *(float2*)&Eo[(size_t)r * Lsz + col] =
                        make_float2(__expf(1.0f - s0), __expf(1.0f - s1));
                }
            }
    } else {
        const float SCALE = 0.125f;
        const int z = zz - Bsz;
        const int b = z >> 3, h = z & 7;
        float acc[2][8][4] = {};
        const float* Ab = g_Q + (size_t)b * Lsz * Dsz + h * DKsz + (size_t)blockIdx.y * 128 * Dsz;
        const float* Bb = g_K + (size_t)b * Lsz * Dsz + h * DKsz + (size_t)blockIdx.x * 128 * Dsz;
        gemm_core<128, 128, true, 2, 8>(Ab, Dsz, Bb, Dsz, DKsz, acc);

        float* Cp = g_S + (size_t)z * Lsz * Lsz;
        int rowBase = blockIdx.y * 128 + (wid & 3) * 32 + (lane >> 2);
        int colBase = blockIdx.x * 128 + (wid >> 2) * 64 + 2 * fcol;

        float rs[2][2] = {};
        #pragma unroll
        for (int mt = 0; mt < 2; mt++)
            #pragma unroll
            for (int nt = 0; nt < 8; nt++) {
                int row = rowBase + mt * 16;
                int col = colBase + nt * 8;
                float p0 = __expf(acc[mt][nt][0] * SCALE);
                float p1 = __expf(acc[mt][nt][1] * SCALE);
                float p2 = __expf(acc[mt][nt][2] * SCALE);
                float p3 = __expf(acc[mt][nt][3] * SCALE);
                *(float2*)&Cp[(size_t)row * Lsz + col]       = make_float2(p0, p1);
                *(float2*)&Cp[(size_t)(row + 8) * Lsz + col] = make_float2(p2, p3);
                rs[mt][0] += p0 + p1;
                rs[mt][1] += p2 + p3;
            }

        #pragma unroll
        for (int mt = 0; mt < 2; mt++)
            #pragma unroll
            for (int hh = 0; hh < 2; hh++) {
                float v = rs[mt][hh];
                v += __shfl_xor_sync(0xffffffffu, v, 1);
                v += __shfl_xor_sync(0xffffffffu, v, 2);
                if (fcol == 0)
                    atomicAdd(&g_Z[(size_t)z * Lsz + rowBase + mt * 16 + hh * 8], v);
            }
    }
}

// ---------------- fused calibrate + ctx GEMM (warp-private transform) ----------------
// 8 warps split along M: warp w owns rows [16w, 16w+16) for BOTH the calibration
// transform and the MMA A-fragments -> transform->MMA needs only __syncwarp().
// One __syncthreads per K-iter (3-stage ring, prefetch after the sync).
__global__ void __launch_bounds__(256, 2) ctx_fused_kernel()
{
    extern __shared__ float sm[];
    float* As = sm;                        // 3 x 128 x 20 (S -> e2 tf32 bits, in place)
    float* Es = sm + 3 * 128 * 20;         // 3 x 128 x 20 (EM)
    float* Bs = sm + 2 * 3 * 128 * 20;     // 3 x 16 x 72  (V)
    float* Z2s = Bs + 3 * 16 * 72;         // 128

    const int tid = threadIdx.x;
    const int lane = tid & 31;
    const int wid = tid >> 5;
    const int z = blockIdx.z;
    const int b = z >> 3, h = z & 7;
    const int q0 = blockIdx.y * 128;

    const float* Sg = g_S + (size_t)z * Lsz * Lsz + (size_t)q0 * Lsz;
    const float* Eg = g_EM + (size_t)b * Lsz * Lsz + (size_t)q0 * Lsz;
    const float* Vg = g_V + (size_t)b * Lsz * Dsz + h * DKsz;

    // transform mapping: warp wid owns tile rows [16*wid, 16*wid+16)
    const int trow = (wid << 4) + (lane >> 1);   // this lane's fixed row
    const int tc0 = (lane & 1) * 8;              // col half within BK=16
    const float grow = g_G[b * Lsz + q0 + trow];
    const float invZ = 1.0f / g_Z[(size_t)z * Lsz + q0 + trow];
    float z2 = 0.f;

    auto prefetch = [&](int it, int s) {
        const int k0 = it * 16;
        float* Asl = As + s * 128 * 20;
        float* Esl = Es + s * 128 * 20;
        float* Bsl = Bs + s * 16 * 72;
        #pragma unroll
        for (int i = 0; i < 2; i++) {
            int idx = tid + i * 256;
            int row = idx >> 2, kq = idx & 3;
            cp_async16(&Asl[row * 20 + kq * 4], Sg + (size_t)row * Lsz + k0 + kq * 4);
            cp_async16(&Esl[row * 20 + kq * 4], Eg + (size_t)row * Lsz + k0 + kq * 4);
        }
        {
            int k = tid >> 4, nq = tid & 15;
            cp_async16(&Bsl[k * 72 + nq * 4], Vg + (size_t)(k0 + k) * Dsz + nq * 4);
        }
        cp_commit();
    };

    const int wm = wid * 16;
    const int frow = lane >> 2, fcol = lane & 3;
    float acc[8][4] = {};

    const int nIter = Lsz / 16;   // 64
    prefetch(0, 0);
    prefetch(1, 1);

    for (int it = 0; it < nIter; it++) {
        if (it + 1 < nIter) cp_wait<1>(); else cp_wait<0>();
        __syncthreads();
        if (it + 2 < nIter) prefetch(it + 2, (it + 2) % 3);

        const int cur = it % 3;
        float* Asl = As + cur * 128 * 20;
        unsigned* Aslu = (unsigned*)Asl;
        const float* Esl = Es + cur * 128 * 20;
        const float* Bsl = Bs + cur * 16 * 72;

        // calibrate this warp's own 16 rows (8 elements per lane)
        #pragma unroll
        for (int j = 0; j < 8; j++) {
            const int c = tc0 + j;
            float p = Asl[trow * 20 + c];
            float w = grow + (1.0f - grow) * Esl[trow * 20 + c];
            unsigned ut = f2tf(__expf(p * invZ * w));
            Aslu[trow * 20 + c] = ut;
            z2 += __uint_as_float(ut);
        }
        __syncwarp();

        #pragma unroll
        for (int ks = 0; ks < 2; ks++) {
            const int kk = ks * 8 + fcol;
            unsigned af[4];
            const int row = wm + frow;
            af[0] = Aslu[row * 20 + kk];
            af[1] = Aslu[(row + 8) * 20 + kk];
            af[2] = Aslu[row * 20 + kk + 4];
            af[3] = Aslu[(row + 8) * 20 + kk + 4];
            #pragma unroll
            for (int nt = 0; nt < 8; nt++) {
                const int n = nt * 8 + frow;
                unsigned bf[2] = { f2tf(Bsl[kk * 72 + n]), f2tf(Bsl[(kk + 4) * 72 + n]) };
                mma_tf32(acc[nt], af, bf);
            }
        }
    }

    // per-row Z2 (lane pair shares a row), all within this warp's 16 rows
    z2 += __shfl_xor_sync(0xffffffffu, z2, 1);
    if ((lane & 1) == 0) Z2s[trow] = z2;
    __syncwarp();

    float* Cp = g_CTX + (size_t)b * Lsz * Dsz + (size_t)q0 * Dsz + h * DKsz;
    const int row = wm + frow;
    const float iza = 1.0f / Z2s[row];
    const float izb = 1.0f / Z2s[row + 8];
    #pragma unroll
    for (int nt = 0; nt < 8; nt++) {
        const int col = nt * 8 + 2 * fcol;
        *(float2*)&Cp[(size_t)row * Dsz + col] =
            make_float2(acc[nt][0] * iza, acc[nt][1] * iza);
        *(float2*)&Cp[(size_t)(row + 8) * Dsz + col] =
            make_float2(acc[nt][2] * izb, acc[nt][3] * izb);
    }
}

// ---------------- gate (+ zero g_Z for the score atomics) ----------------
__global__ void gate_kernel(const float* __restrict__ query,
                            const float* __restrict__ gw,
                            const float* __restrict__ gb)
{
    int gidx = blockIdx.x * blockDim.x + threadIdx.x;
    if (gidx < Bsz * Hsz * Lsz) g_Z[gidx] = 0.f;

    int warp = gidx >> 5;
    int lane = threadIdx.x & 31;
    if (warp >= Bsz * Lsz) return;
    const float* row = query + (size_t)warp * Dsz;
    float s = 0.f;
    for (int d = lane; d < Dsz; d += 32) s += row[d] * gw[d];
    #pragma unroll
    for (int o = 16; o; o >>= 1) s += __shfl_xor_sync(0xffffffffu, s, o);
    if (lane == 0) g_G[warp] = 1.0f / (1.0f + __expf(-(s + gb[0])));
}

// ---------------- launch ----------------
extern "C" void kernel_launch(void* const* d_in, const int* in_sizes, int n_in,
                              void* d_out, int out_size)
{
    const float* query   = (const float*)d_in[0];
    const float* key     = (const float*)d_in[1];
    const float* value   = (const float*)d_in[2];
    const float* wq_w    = (const float*)d_in[3];
    const float* wq_b    = (const float*)d_in[4];
    const float* wk_w    = (const float*)d_in[5];
    const float* wk_b    = (const float*)d_in[6];
    const float* wv_w    = (const float*)d_in[7];
    const float* wv_b    = (const float*)d_in[8];
    const float* dense_w = (const float*)d_in[9];
    const float* dense_b = (const float*)d_in[10];
    const float* gate_w  = (const float*)d_in[11];
    const float* gate_b  = (const float*)d_in[12];
    const float* mp_wq_w = (const float*)d_in[13];
    const float* mp_wq_b = (const float*)d_in[14];
    const float* mp_wk_w = (const float*)d_in[15];
    const float* mp_wk_b = (const float*)d_in[16];

    float* out   = (float*)d_out;
    float* m_out = out + (size_t)Bsz * Lsz * Dsz;

    float *pQ, *pK, *pV, *pQP, *pKP, *pCTX;
    cudaGetSymbolAddress((void**)&pQ,   g_Q);
    cudaGetSymbolAddress((void**)&pK,   g_K);
    cudaGetSymbolAddress((void**)&pV,   g_V);
    cudaGetSymbolAddress((void**)&pQP,  g_QP);
    cudaGetSymbolAddress((void**)&pKP,  g_KP);
    cudaGetSymbolAddress((void**)&pCTX, g_CTX);

    static int attr_set = 0;
    if (!attr_set) {
        cudaFuncSetAttribute(proj_gemm_kernel,
                             cudaFuncAttributeMaxDynamicSharedMemorySize, PROJ_SMEM);
        cudaFuncSetAttribute(ms_gemm_kernel,
                             cudaFuncAttributeMaxDynamicSharedMemorySize, NTG_SMEM);
        cudaFuncSetAttribute(ctx_fused_kernel,
                             cudaFuncAttributeMaxDynamicSharedMemorySize, CTXF_SMEM);
        attr_set = 1;
    }

    dim3 t256(256);

    ProjArgs pa;
    pa.A[0] = query; pa.W[0] = wq_w;    pa.bias[0] = wq_b;    pa.C[0] = pQ;
    pa.A[1] = key;   pa.W[1] = wk_w;    pa.bias[1] = wk_b;    pa.C[1] = pK;
    pa.A[2] = value; pa.W[2] = wv_w;    pa.bias[2] = wv_b;    pa.C[2] = pV;
    pa.A[3] = query; pa.W[3] = mp_wq_w; pa.bias[3] = mp_wq_b; pa.C[3] = pQP;
    pa.A[4] = key;   pa.W[4] = mp_wk_w; pa.bias[4] = mp_wk_b; pa.C[4] = pKP;
    proj_gemm_kernel<<<dim3(4, 32, 5), t256, PROJ_SMEM>>>(pa, Dsz, Dsz);

    gate_kernel<<<(Bsz * Lsz * 32) / 256, t256>>>(query, gate_w, gate_b);

    ms_gemm_kernel<<<dim3(8, 8, Bsz + Bsz * Hsz), t256, NTG_SMEM>>>(m_out);

    ctx_fused_kernel<<<dim3(1, 8, Bsz * Hsz), t256, CTXF_SMEM>>>();

    ProjArgs da;
    da.A[0] = pCTX; da.W[0] = dense_w; da.bias[0] = dense_b; da.C[0] = out;
    proj_gemm_kernel<<<dim3(4, 32, 1), t256, PROJ_SMEM>>>(da, Dsz, Dsz);
}

// round 8
// speedup vs baseline: 1.2729x; 1.2729x over previous
#include <cuda_runtime.h>
#include <cuda_bf16.h>
#include <math.h>

#define Bsz 4
#define Lsz 1024
#define Dsz 512
#define Hsz 8
#define DKsz 64

// ---------------- scratch (static device globals; no allocation) ----------------
__device__ float g_Q[Bsz*Lsz*Dsz];      // tf32-prerounded
__device__ float g_K[Bsz*Lsz*Dsz];      // tf32-prerounded
__device__ float g_V[Bsz*Lsz*Dsz];      // tf32-prerounded
__device__ float g_QP[Bsz*Lsz*Dsz];     // tf32-prerounded
__device__ float g_KP[Bsz*Lsz*Dsz];     // tf32-prerounded
__device__ __nv_bfloat16 g_EMb[Bsz*Lsz*Lsz];              // exp(1-m), bf16
__device__ float g_G[Bsz*Lsz];
__device__ __nv_bfloat16 g_Sb[(size_t)Bsz*Hsz*Lsz*Lsz];   // exp(scores), bf16 (67MB)
__device__ float g_Z[Bsz*Hsz*Lsz];
__device__ float g_CTX[Bsz*Lsz*Dsz];

// ---------------- helpers ----------------
__device__ __forceinline__ unsigned f2tf(float f) {
    unsigned u;
    asm("cvt.rna.tf32.f32 %0, %1;" : "=r"(u) : "f"(f));
    return u;
}
__device__ __forceinline__ float tf32r(float f) { return __uint_as_float(f2tf(f)); }

__device__ __forceinline__ void mma_tf32(float c[4], const unsigned a[4], const unsigned b[2]) {
    asm volatile(
        "mma.sync.aligned.m16n8k8.row.col.f32.tf32.tf32.f32 "
        "{%0,%1,%2,%3}, {%4,%5,%6,%7}, {%8,%9}, {%0,%1,%2,%3};"
        : "+f"(c[0]), "+f"(c[1]), "+f"(c[2]), "+f"(c[3])
        : "r"(a[0]), "r"(a[1]), "r"(a[2]), "r"(a[3]), "r"(b[0]), "r"(b[1]));
}

__device__ __forceinline__ void cp_async16(void* smem, const void* gmem) {
    unsigned saddr = (unsigned)__cvta_generic_to_shared(smem);
    asm volatile("cp.async.cg.shared.global [%0], [%1], 16;" :: "r"(saddr), "l"(gmem));
}
__device__ __forceinline__ void cp_commit() { asm volatile("cp.async.commit_group;"); }
template<int N>
__device__ __forceinline__ void cp_wait() { asm volatile("cp.async.wait_group %0;" :: "n"(N)); }

// ---------------- tf32 GEMM core, 4-stage pipeline, prefetch-before-sync (race-free) ----
// Stage (it+2)&3 was last read at iter it-2; every thread here passed sync(it-1),
// which proves all threads finished compute(it-2). Early cp.async issue, one sync/iter.
template<int BM, int BN, bool BT, int MT, int NT, bool NOCVT>
__device__ __forceinline__ void gemm_core(
    const float* __restrict__ A, int lda,
    const float* __restrict__ B, int ldb,
    int K, float (&acc)[MT][NT][4])
{
    constexpr int BK = 16;
    constexpr int APITCH = BK + 4;
    constexpr int BPITCH = BT ? (BK + 4) : (BN + 8);
    constexpr int BROWS  = BT ? BN : BK;

    extern __shared__ float dynsm[];
    float* As = dynsm;
    float* Bs = dynsm + 4 * BM * APITCH;

    const int tid = threadIdx.x;
    const int lane = tid & 31;
    const int wid = tid >> 5;
    const int wm0 = (wid & 3) * (BM / 4);
    const int wn0 = (wid >> 2) * (BN / 2);

    constexpr int ALD = (BM * BK / 4) / 256;
    constexpr int BLD = (BT ? (BN * BK / 4) : (BK * BN / 4)) / 256;

    auto prefetch = [&](int k0, int s) {
        float* Asl = As + s * BM * APITCH;
        float* Bsl = Bs + s * BROWS * BPITCH;
        #pragma unroll
        for (int i = 0; i < ALD; i++) {
            int idx = tid + i * 256;
            int row = idx >> 2, kq = idx & 3;
            cp_async16(&Asl[row * APITCH + kq * 4], A + (size_t)row * lda + k0 + kq * 4);
        }
        #pragma unroll
        for (int i = 0; i < BLD; i++) {
            int idx = tid + i * 256;
            if constexpr (BT) {
                int row = idx >> 2, kq = idx & 3;
                cp_async16(&Bsl[row * BPITCH + kq * 4], B + (size_t)row * ldb + k0 + kq * 4);
            } else {
                int k = idx / (BN / 4), nq = idx % (BN / 4);
                cp_async16(&Bsl[k * BPITCH + nq * 4], B + (size_t)(k0 + k) * ldb + nq * 4);
            }
        }
        cp_commit();
    };

    const int nIter = K / BK;
    prefetch(0, 0);
    if (nIter > 1) prefetch(BK, 1);

    for (int it = 0; it < nIter; it++) {
        if (it + 2 < nIter) { prefetch((it + 2) * BK, (it + 2) & 3); cp_wait<2>(); }
        else if (it + 1 < nIter) { cp_wait<1>(); }
        else { cp_wait<0>(); }
        __syncthreads();

        const int cur = it & 3;
        const float* Asl = As + cur * BM * APITCH;
        const float* Bsl = Bs + cur * BROWS * BPITCH;
        const unsigned* Aslu = (const unsigned*)Asl;
        const unsigned* Bslu = (const unsigned*)Bsl;

        #pragma unroll
        for (int ks = 0; ks < 2; ks++) {
            unsigned af[MT][4];
            unsigned bf[NT][2];
            const int kk = ks * 8 + (lane & 3);
            #pragma unroll
            for (int mt = 0; mt < MT; mt++) {
                int row = wm0 + mt * 16 + (lane >> 2);
                if constexpr (NOCVT) {
                    af[mt][0] = Aslu[row * APITCH + kk];
                    af[mt][1] = Aslu[(row + 8) * APITCH + kk];
                    af[mt][2] = Aslu[row * APITCH + kk + 4];
                    af[mt][3] = Aslu[(row + 8) * APITCH + kk + 4];
                } else {
                    af[mt][0] = f2tf(Asl[row * APITCH + kk]);
                    af[mt][1] = f2tf(Asl[(row + 8) * APITCH + kk]);
                    af[mt][2] = f2tf(Asl[row * APITCH + kk + 4]);
                    af[mt][3] = f2tf(Asl[(row + 8) * APITCH + kk + 4]);
                }
            }
            #pragma unroll
            for (int nt = 0; nt < NT; nt++) {
                int n = wn0 + nt * 8 + (lane >> 2);
                if constexpr (BT) {
                    if constexpr (NOCVT) {
                        bf[nt][0] = Bslu[n * BPITCH + kk];
                        bf[nt][1] = Bslu[n * BPITCH + kk + 4];
                    } else {
                        bf[nt][0] = f2tf(Bsl[n * BPITCH + kk]);
                        bf[nt][1] = f2tf(Bsl[n * BPITCH + kk + 4]);
                    }
                } else {
                    if constexpr (NOCVT) {
                        bf[nt][0] = Bslu[kk * BPITCH + n];
                        bf[nt][1] = Bslu[(kk + 4) * BPITCH + n];
                    } else {
                        bf[nt][0] = f2tf(Bsl[kk * BPITCH + n]);
                        bf[nt][1] = f2tf(Bsl[(kk + 4) * BPITCH + n]);
                    }
                }
            }
            #pragma unroll
            for (int mt = 0; mt < MT; mt++)
                #pragma unroll
                for (int nt = 0; nt < NT; nt++)
                    mma_tf32(acc[mt][nt], af[mt], bf[nt]);
        }
    }
}

// smem byte sizes (4-stage)
#define PROJ_SMEM  ((4*128*20 + 4*16*136) * 4)   // 75776
#define NTG_SMEM   ((4*128*20 * 2) * 4)          // 81920
#define CTX_S_BYTES   (4 * 128 * 24 * 2)         // 24576 (bf16)
#define CTX_E_BYTES   (4 * 128 * 24 * 2)         // 24576 (bf16)
#define CTX_V_BYTES   (4 * 16 * 72 * 4)          // 18432 (fp32)
#define CTXF_SMEM  (CTX_S_BYTES + CTX_E_BYTES + CTX_V_BYTES)  // 67584

// ---------------- batched projections / dense ----------------
struct ProjArgs {
    const float* A[5];
    const float* W[5];
    const float* bias[5];
    float* C[5];
};

__global__ void __launch_bounds__(256, 2) proj_gemm_kernel(ProjArgs args, int N, int K, int roundOut)
{
    const int z = blockIdx.z;
    float acc[2][8][4] = {};
    const float* Ab = args.A[z] + (size_t)blockIdx.y * 128 * K;
    const float* Bb = args.W[z] + blockIdx.x * 128;
    gemm_core<128, 128, false, 2, 8, false>(Ab, K, Bb, N, K, acc);

    const float* bias = args.bias[z];
    float* C = args.C[z];
    int lane = threadIdx.x & 31, wid = threadIdx.x >> 5;
    int rowBase = blockIdx.y * 128 + (wid & 3) * 32 + (lane >> 2);
    int colBase = blockIdx.x * 128 + (wid >> 2) * 64 + 2 * (lane & 3);
    #pragma unroll
    for (int mt = 0; mt < 2; mt++)
        #pragma unroll
        for (int nt = 0; nt < 8; nt++) {
            int row = rowBase + mt * 16;
            int col = colBase + nt * 8;
            float b0 = bias[col], b1 = bias[col + 1];
            float v0 = acc[mt][nt][0] + b0, v1 = acc[mt][nt][1] + b1;
            float v2 = acc[mt][nt][2] + b0, v3 = acc[mt][nt][3] + b1;
            if (roundOut) {  // outputs consumed only as tf32 MMA operands
                v0 = tf32r(v0); v1 = tf32r(v1); v2 = tf32r(v2); v3 = tf32r(v3);
            }
            *(float2*)&C[(size_t)row * N + col]       = make_float2(v0, v1);
            *(float2*)&C[(size_t)(row + 8) * N + col] = make_float2(v2, v3);
        }
}

// ---------------- merged m + score GEMM launch (NOCVT: inputs tf32-prerounded) ----------
__global__ void __launch_bounds__(256, 2) ms_gemm_kernel(float* __restrict__ m_out)
{
    const int zz = blockIdx.z;
    int lane = threadIdx.x & 31, wid = threadIdx.x >> 5;
    int fcol = lane & 3;

    if (zz < Bsz) {
        const float SCALE = 0.04419417382415922f; // 1/sqrt(512)
        const int zb = zz;
        float acc[2][8][4] = {};
        const float* Ab = g_QP + (size_t)zb * Lsz * Dsz + (size_t)blockIdx.y * 128 * Dsz;
        const float* Bb = g_KP + (size_t)zb * Lsz * Dsz + (size_t)blockIdx.x * 128 * Dsz;
        gemm_core<128, 128, true, 2, 8, true>(Ab, Dsz, Bb, Dsz, Dsz, acc);

        float* Mo = m_out + (size_t)zb * Lsz * Lsz;
        __nv_bfloat16* Eo = g_EMb + (size_t)zb * Lsz * Lsz;
        int rowBase = blockIdx.y * 128 + (wid & 3) * 32 + (lane >> 2);
        int colBase = blockIdx.x * 128 + (wid >> 2) * 64 + 2 * fcol;
        #pragma unroll
        for (int mt = 0; mt < 2; mt++)
            #pragma unroll
            for (int nt = 0; nt < 8; nt++) {
                int row = rowBase + mt * 16;
                int col = colBase + nt * 8;
                #pragma unroll
                for (int h = 0; h < 2; h++) {
                    int r = row + h * 8;
                    float s0 = 1.0f / (1.0f + __expf(-acc[mt][nt][2*h] * SCALE));
                    float s1 = 1.0f / (1.0f + __expf(-acc[mt][nt][2*h+1] * SCALE));
                    *(float2*)&Mo[(size_t)r * Lsz + col] = make_float2(s0, s1);
                    *(__nv_bfloat162*)&Eo[(size_t)r * Lsz + col] =
                        __float22bfloat162_rn(make_float2(__expf(1.0f - s0), __expf(1.0f - s1)));
                }
            }
    } else {
        const float SCALE = 0.125f;
        const int z = zz - Bsz;
        const int b = z >> 3, h = z & 7;
        float acc[2][8][4] = {};
        const float* Ab = g_Q + (size_t)b * Lsz * Dsz + h * DKsz + (size_t)blockIdx.y * 128 * Dsz;
        const float* Bb = g_K + (size_t)b * Lsz * Dsz + h * DKsz + (size_t)blockIdx.x * 128 * Dsz;
        gemm_core<128, 128, true, 2, 8, true>(Ab, Dsz, Bb, Dsz, DKsz, acc);

        __nv_bfloat16* Cp = g_Sb + (size_t)z * Lsz * Lsz;
        int rowBase = blockIdx.y * 128 + (wid & 3) * 32 + (lane >> 2);
        int colBase = blockIdx.x * 128 + (wid >> 2) * 64 + 2 * fcol;

        float rs[2][2] = {};
        #pragma unroll
        for (int mt = 0; mt < 2; mt++)
            #pragma unroll
            for (int nt = 0; nt < 8; nt++) {
                int row = rowBase + mt * 16;
                int col = colBase + nt * 8;
                float p0 = __expf(acc[mt][nt][0] * SCALE);
                float p1 = __expf(acc[mt][nt][1] * SCALE);
                float p2 = __expf(acc[mt][nt][2] * SCALE);
                float p3 = __expf(acc[mt][nt][3] * SCALE);
                *(__nv_bfloat162*)&Cp[(size_t)row * Lsz + col] =
                    __float22bfloat162_rn(make_float2(p0, p1));
                *(__nv_bfloat162*)&Cp[(size_t)(row + 8) * Lsz + col] =
                    __float22bfloat162_rn(make_float2(p2, p3));
                rs[mt][0] += p0 + p1;
                rs[mt][1] += p2 + p3;
            }

        #pragma unroll
        for (int mt = 0; mt < 2; mt++)
            #pragma unroll
            for (int hh = 0; hh < 2; hh++) {
                float v = rs[mt][hh];
                v += __shfl_xor_sync(0xffffffffu, v, 1);
                v += __shfl_xor_sync(0xffffffffu, v, 2);
                if (fcol == 0)
                    atomicAdd(&g_Z[(size_t)z * Lsz + rowBase + mt * 16 + hh * 8], v);
            }
    }
}

// ---------------- fused calibrate + ctx GEMM v2 ----------------
// bf16 S/EM smem tiles -> per-lane register transform (lane loads exactly its
// MMA A-frag elements) -> MMA. Z2 per-lane, quad-reduced at exit. V prerounded.
__global__ void __launch_bounds__(256, 2) ctx_fused_kernel()
{
    extern __shared__ char smc[];
    __nv_bfloat16* Ss = (__nv_bfloat16*)smc;                    // 4 x 128 x 24
    __nv_bfloat16* Es = (__nv_bfloat16*)(smc + CTX_S_BYTES);    // 4 x 128 x 24
    unsigned* Vu = (unsigned*)(smc + CTX_S_BYTES + CTX_E_BYTES);// 4 x 16 x 72 (tf32 bits)
    float* Vf = (float*)Vu;

    const int tid = threadIdx.x;
    const int lane = tid & 31;
    const int wid = tid >> 5;
    const int z = blockIdx.z;
    const int b = z >> 3, h = z & 7;
    const int q0 = blockIdx.y * 128;

    const __nv_bfloat16* Sg = g_Sb + (size_t)z * Lsz * Lsz + (size_t)q0 * Lsz;
    const __nv_bfloat16* Eg = g_EMb + (size_t)b * Lsz * Lsz + (size_t)q0 * Lsz;
    const float* Vg = g_V + (size_t)b * Lsz * Dsz + h * DKsz;

    const int wm = wid * 16;
    const int frow = lane >> 2, fcol = lane & 3;
    const int r0 = wm + frow, r1 = r0 + 8;

    // x = p * (ga + gc*em)  with ga = g*invZ, gc = (1-g)*invZ
    const float g0 = g_G[b * Lsz + q0 + r0];
    const float g1 = g_G[b * Lsz + q0 + r1];
    const float iz0 = 1.0f / g_Z[(size_t)z * Lsz + q0 + r0];
    const float iz1 = 1.0f / g_Z[(size_t)z * Lsz + q0 + r1];
    const float ga0 = g0 * iz0, gc0 = (1.0f - g0) * iz0;
    const float ga1 = g1 * iz1, gc1 = (1.0f - g1) * iz1;
    float z2a = 0.f, z2b = 0.f;

    auto prefetch = [&](int it, int s) {
        const int k0 = it * 16;
        __nv_bfloat16* Sl = Ss + s * 128 * 24;
        __nv_bfloat16* El = Es + s * 128 * 24;
        float* Vl = Vf + s * 16 * 72;
        {
            int row = tid >> 1, ch = tid & 1;   // 128 rows x 2 x 16B (8 bf16)
            cp_async16(&Sl[row * 24 + ch * 8], Sg + (size_t)row * Lsz + k0 + ch * 8);
            cp_async16(&El[row * 24 + ch * 8], Eg + (size_t)row * Lsz + k0 + ch * 8);
        }
        {
            int vr = tid >> 4, vc = tid & 15;   // 16 rows x 16 x 16B
            cp_async16(&Vl[vr * 72 + vc * 4], Vg + (size_t)(k0 + vr) * Dsz + vc * 4);
        }
        cp_commit();
    };

    float acc[8][4] = {};
    const int nIter = Lsz / 16;   // 64
    prefetch(0, 0);
    prefetch(1, 1);

    for (int it = 0; it < nIter; it++) {
        if (it + 2 < nIter) { prefetch(it + 2, (it + 2) & 3); cp_wait<2>(); }
        else if (it + 1 < nIter) { cp_wait<1>(); }
        else { cp_wait<0>(); }
        __syncthreads();

        const int cur = it & 3;
        const __nv_bfloat16* Sl = Ss + cur * 128 * 24;
        const __nv_bfloat16* El = Es + cur * 128 * 24;
        const unsigned* Vl = Vu + cur * 16 * 72;

        #pragma unroll
        for (int ks = 0; ks < 2; ks++) {
            const int kk = ks * 8 + fcol;

            // transform exactly this lane's A-frag elements, in registers
            float p00 = __bfloat162float(Sl[r0 * 24 + kk]);
            float p10 = __bfloat162float(Sl[r1 * 24 + kk]);
            float p01 = __bfloat162float(Sl[r0 * 24 + kk + 4]);
            float p11 = __bfloat162float(Sl[r1 * 24 + kk + 4]);
            float e00 = __bfloat162float(El[r0 * 24 + kk]);
            float e10 = __bfloat162float(El[r1 * 24 + kk]);
            float e01 = __bfloat162float(El[r0 * 24 + kk + 4]);
            float e11 = __bfloat162float(El[r1 * 24 + kk + 4]);

            unsigned af[4];
            af[0] = f2tf(__expf(p00 * fmaf(gc0, e00, ga0)));
            af[1] = f2tf(__expf(p10 * fmaf(gc1, e10, ga1)));
            af[2] = f2tf(__expf(p01 * fmaf(gc0, e01, ga0)));
            af[3] = f2tf(__expf(p11 * fmaf(gc1, e11, ga1)));
            z2a += __uint_as_float(af[0]) + __uint_as_float(af[2]);
            z2b += __uint_as_float(af[1]) + __uint_as_float(af[3]);

            #pragma unroll
            for (int nt = 0; nt < 8; nt++) {
                const int n = nt * 8 + frow;
                unsigned bf[2] = { Vl[kk * 72 + n], Vl[(kk + 4) * 72 + n] };
                mma_tf32(acc[nt], af, bf);
            }
        }
    }

    // per-row Z2: quad (fcol 0..3) covers all 8 cols of each k-step
    z2a += __shfl_xor_sync(0xffffffffu, z2a, 1);
    z2a += __shfl_xor_sync(0xffffffffu, z2a, 2);
    z2b += __shfl_xor_sync(0xffffffffu, z2b, 1);
    z2b += __shfl_xor_sync(0xffffffffu, z2b, 2);
    const float iza = 1.0f / z2a;
    const float izb = 1.0f / z2b;

    float* Cp = g_CTX + (size_t)b * Lsz * Dsz + (size_t)q0 * Dsz + h * DKsz;
    #pragma unroll
    for (int nt = 0; nt < 8; nt++) {
        const int col = nt * 8 + 2 * fcol;
        *(float2*)&Cp[(size_t)r0 * Dsz + col] =
            make_float2(acc[nt][0] * iza, acc[nt][1] * iza);
        *(float2*)&Cp[(size_t)r1 * Dsz + col] =
            make_float2(acc[nt][2] * izb, acc[nt][3] * izb);
    }
}

// ---------------- gate (+ zero g_Z for the score atomics) ----------------
__global__ void gate_kernel(const float* __restrict__ query,
                            const float* __restrict__ gw,
                            const float* __restrict__ gb)
{
    int gidx = blockIdx.x * blockDim.x + threadIdx.x;
    if (gidx < Bsz * Hsz * Lsz) g_Z[gidx] = 0.f;

    int warp = gidx >> 5;
    int lane = threadIdx.x & 31;
    if (warp >= Bsz * Lsz) return;
    const float* row = query + (size_t)warp * Dsz;
    float s = 0.f;
    for (int d = lane; d < Dsz; d += 32) s += row[d] * gw[d];
    #pragma unroll
    for (int o = 16; o; o >>= 1) s += __shfl_xor_sync(0xffffffffu, s, o);
    if (lane == 0) g_G[warp] = 1.0f / (1.0f + __expf(-(s + gb[0])));
}

// ---------------- launch ----------------
extern "C" void kernel_launch(void* const* d_in, const int* in_sizes, int n_in,
                              void* d_out, int out_size)
{
    const float* query   = (const float*)d_in[0];
    const float* key     = (const float*)d_in[1];
    const float* value   = (const float*)d_in[2];
    const float* wq_w    = (const float*)d_in[3];
    const float* wq_b    = (const float*)d_in[4];
    const float* wk_w    = (const float*)d_in[5];
    const float* wk_b    = (const float*)d_in[6];
    const float* wv_w    = (const float*)d_in[7];
    const float* wv_b    = (const float*)d_in[8];
    const float* dense_w = (const float*)d_in[9];
    const float* dense_b = (const float*)d_in[10];
    const float* gate_w  = (const float*)d_in[11];
    const float* gate_b  = (const float*)d_in[12];
    const float* mp_wq_w = (const float*)d_in[13];
    const float* mp_wq_b = (const float*)d_in[14];
    const float* mp_wk_w = (const float*)d_in[15];
    const float* mp_wk_b = (const float*)d_in[16];

    float* out   = (float*)d_out;
    float* m_out = out + (size_t)Bsz * Lsz * Dsz;

    float *pQ, *pK, *pV, *pQP, *pKP, *pCTX;
    cudaGetSymbolAddress((void**)&pQ,   g_Q);
    cudaGetSymbolAddress((void**)&pK,   g_K);
    cudaGetSymbolAddress((void**)&pV,   g_V);
    cudaGetSymbolAddress((void**)&pQP,  g_QP);
    cudaGetSymbolAddress((void**)&pKP,  g_KP);
    cudaGetSymbolAddress((void**)&pCTX, g_CTX);

    static int attr_set = 0;
    if (!attr_set) {
        cudaFuncSetAttribute(proj_gemm_kernel,
                             cudaFuncAttributeMaxDynamicSharedMemorySize, PROJ_SMEM);
        cudaFuncSetAttribute(ms_gemm_kernel,
                             cudaFuncAttributeMaxDynamicSharedMemorySize, NTG_SMEM);
        cudaFuncSetAttribute(ctx_fused_kernel,
                             cudaFuncAttributeMaxDynamicSharedMemorySize, CTXF_SMEM);
        attr_set = 1;
    }

    dim3 t256(256);

    ProjArgs pa;
    pa.A[0] = query; pa.W[0] = wq_w;    pa.bias[0] = wq_b;    pa.C[0] = pQ;
    pa.A[1] = key;   pa.W[1] = wk_w;    pa.bias[1] = wk_b;    pa.C[1] = pK;
    pa.A[2] = value; pa.W[2] = wv_w;    pa.bias[2] = wv_b;    pa.C[2] = pV;
    pa.A[3] = query; pa.W[3] = mp_wq_w; pa.bias[3] = mp_wq_b; pa.C[3] = pQP;
    pa.A[4] = key;   pa.W[4] = mp_wk_w; pa.bias[4] = mp_wk_b; pa.C[4] = pKP;
    proj_gemm_kernel<<<dim3(4, 32, 5), t256, PROJ_SMEM>>>(pa, Dsz, Dsz, 1);

    gate_kernel<<<(Bsz * Lsz * 32) / 256, t256>>>(query, gate_w, gate_b);

    ms_gemm_kernel<<<dim3(8, 8, Bsz + Bsz * Hsz), t256, NTG_SMEM>>>(m_out);

    ctx_fused_kernel<<<dim3(1, 8, Bsz * Hsz), t256, CTXF_SMEM>>>();

    ProjArgs da;
    da.A[0] = pCTX; da.W[0] = dense_w; da.bias[0] = dense_b; da.C[0] = out;
    proj_gemm_kernel<<<dim3(4, 32, 1), t256, PROJ_SMEM>>>(da, Dsz, Dsz, 0);
}